// round 9
// baseline (speedup 1.0000x reference)
#include <cuda_runtime.h>
#include <math.h>

#define BATCH 4096
#define DIM   128
#define KNBR  200
#define NCLS  1000
#define GC    0.5f          // 1/(2*sigma^2), sigma=1
#define THREADS 256
#define WARPS   (THREADS/32)
#define GSIZE   16
#define NGROUPS (THREADS/GSIZE)          // 16 groups of 16 lanes
#define FULL_ITERS (KNBR / NGROUPS)      // 12 full iterations
#define TAILG (KNBR - NGROUPS*FULL_ITERS) // 8 tail groups (= warps 0..3)

#define N_CENTRES_ELEMS 12800000
#define N_FEAT_ELEMS    524288
#define N_NBR_ELEMS     819200
#define N_100K          100000

#define FLT_MIN_NORMAL 1.17549435082228750797e-38f   // 2^-126

// Emulate aarch64 FPCR.FZ semantics: any op result that is subnormal flushes to 0.
__device__ __forceinline__ float ftz(float v) {
    return (v < FLT_MIN_NORMAL) ? 0.0f : v;   // v >= 0 in all our uses
}

__global__ __launch_bounds__(THREADS)
void gaussian_kernels_kernel(const float* __restrict__ features,
                             const float* __restrict__ centres,
                             const void*  __restrict__ cand0,   // weight OR centre_labels
                             const void*  __restrict__ cand1,   // the other one
                             const int*   __restrict__ neighbours,
                             float*       __restrict__ out)
{
    __shared__ alignas(16) float p[NCLS];
    __shared__ float warp_sums[WARPS];

    const int b    = blockIdx.x;
    const int tid  = threadIdx.x;
    const int lane = tid & 31;
    const int grp  = tid >> 4;          // 0..15 : 16-lane group id
    const int sub  = tid & 15;          // lane within group
    const int warp = tid >> 5;

    // ---- disambiguate weight vs centre_labels by bit pattern (deterministic) ----
    const unsigned int* a0p = (const unsigned int*)cand0;
    const bool first_is_labels =
        (a0p[0] < 1000u) && (a0p[1] < 1000u) && (a0p[2] < 1000u) && (a0p[3] < 1000u);
    const float* weight        = first_is_labels ? (const float*)cand1 : (const float*)cand0;
    const int*   centre_labels = first_is_labels ? (const int*)cand0   : (const int*)cand1;

    // zero the class histogram (vectorized: 250 float4s)
    if (tid < NCLS/4) ((float4*)p)[tid] = make_float4(0.f, 0.f, 0.f, 0.f);

    // each lane holds 8 dims: float4s at [sub] and [sub+16].
    // For fixed slice j, a group's 16 lanes cover a contiguous 256B (2 lines).
    const float4* frow = reinterpret_cast<const float4*>(features + (size_t)b * DIM);
    const float4 f0 = frow[sub];
    const float4 f1 = frow[sub + GSIZE];

    __syncthreads();

    const int* nb = neighbours + (size_t)b * KNBR;

    // ---- depth-2 software pipeline over 12 iterations ----
    int ia = nb[grp];                 // iteration 0 index
    int ib = nb[grp + NGROUPS];       // iteration 1 index
    const float4* ra = reinterpret_cast<const float4*>(centres + (size_t)ia * DIM);
    float4 a0 = ra[sub], a1 = ra[sub + GSIZE];
    const float4* rb = reinterpret_cast<const float4*>(centres + (size_t)ib * DIM);
    float4 b0 = rb[sub], b1 = rb[sub + GSIZE];

    #pragma unroll
    for (int i = 0; i < FULL_ITERS; i++) {
        int ic = 0;
        float4 n0, n1;
        if (i + 2 < FULL_ITERS) {
            ic = nb[grp + NGROUPS * (i + 2)];
            const float4* rc = reinterpret_cast<const float4*>(centres + (size_t)ic * DIM);
            n0 = rc[sub];
            n1 = rc[sub + GSIZE];
        }

        // compute squared distance against tile A (2 independent accumulators)
        float s0 = 0.f, s1 = 0.f;
        float dx;
        dx = f0.x - a0.x; s0 = fmaf(dx, dx, s0);
        dx = f0.y - a0.y; s0 = fmaf(dx, dx, s0);
        dx = f0.z - a0.z; s0 = fmaf(dx, dx, s0);
        dx = f0.w - a0.w; s0 = fmaf(dx, dx, s0);
        dx = f1.x - a1.x; s1 = fmaf(dx, dx, s1);
        dx = f1.y - a1.y; s1 = fmaf(dx, dx, s1);
        dx = f1.z - a1.z; s1 = fmaf(dx, dx, s1);
        dx = f1.w - a1.w; s1 = fmaf(dx, dx, s1);
        float s = s0 + s1;

        // reduce within the 16-lane group
        s += __shfl_xor_sync(0xffffffffu, s, 8);
        s += __shfl_xor_sync(0xffffffffu, s, 4);
        s += __shfl_xor_sync(0xffffffffu, s, 2);
        s += __shfl_xor_sync(0xffffffffu, s, 1);

        if (sub == 0) {
            const float w   = weight[ia];
            const int   lbl = centre_labels[ia];
            // reference semantics (aarch64 FZ): subnormal op results flush to 0
            const float e1   = ftz(expf(-s * GC));
            const float kern = ftz(e1 * expf(w));
            if (kern != 0.0f) atomicAdd(&p[lbl], kern);
        }

        // rotate the pipeline
        ia = ib; a0 = b0; a1 = b1;
        if (i + 2 < FULL_ITERS) { ib = ic; b0 = n0; b1 = n1; }
    }

    // tail: neighbours 192..199, live only for groups 0..7 (warps 0..3, uniform branch)
    if (grp < TAILG) {
        const int n = nb[grp + NGROUPS * FULL_ITERS];
        const float4* rc = reinterpret_cast<const float4*>(centres + (size_t)n * DIM);
        const float4 t0 = rc[sub];
        const float4 t1 = rc[sub + GSIZE];
        float s0 = 0.f, s1 = 0.f;
        float dx;
        dx = f0.x - t0.x; s0 = fmaf(dx, dx, s0);
        dx = f0.y - t0.y; s0 = fmaf(dx, dx, s0);
        dx = f0.z - t0.z; s0 = fmaf(dx, dx, s0);
        dx = f0.w - t0.w; s0 = fmaf(dx, dx, s0);
        dx = f1.x - t1.x; s1 = fmaf(dx, dx, s1);
        dx = f1.y - t1.y; s1 = fmaf(dx, dx, s1);
        dx = f1.z - t1.z; s1 = fmaf(dx, dx, s1);
        dx = f1.w - t1.w; s1 = fmaf(dx, dx, s1);
        float s = s0 + s1;
        s += __shfl_xor_sync(0xffffffffu, s, 8);
        s += __shfl_xor_sync(0xffffffffu, s, 4);
        s += __shfl_xor_sync(0xffffffffu, s, 2);
        s += __shfl_xor_sync(0xffffffffu, s, 1);
        if (sub == 0) {
            const float w   = weight[n];
            const int   lbl = centre_labels[n];
            const float e1   = ftz(expf(-s * GC));
            const float kern = ftz(e1 * expf(w));
            if (kern != 0.0f) atomicAdd(&p[lbl], kern);
        }
    }

    __syncthreads();

    // epsilon-clamp empty bins + row sum, vectorized over 250 float4s
    float local = 0.0f;
    float4 v = make_float4(0.f, 0.f, 0.f, 0.f);
    if (tid < NCLS/4) {
        v = ((const float4*)p)[tid];
        v.x = (v.x == 0.0f) ? 1e-10f : v.x;
        v.y = (v.y == 0.0f) ? 1e-10f : v.y;
        v.z = (v.z == 0.0f) ? 1e-10f : v.z;
        v.w = (v.w == 0.0f) ? 1e-10f : v.w;
        local = (v.x + v.y) + (v.z + v.w);
    }
    // block reduce
    local += __shfl_xor_sync(0xffffffffu, local, 16);
    local += __shfl_xor_sync(0xffffffffu, local, 8);
    local += __shfl_xor_sync(0xffffffffu, local, 4);
    local += __shfl_xor_sync(0xffffffffu, local, 2);
    local += __shfl_xor_sync(0xffffffffu, local, 1);
    if (lane == 0) warp_sums[warp] = local;
    __syncthreads();

    float total = 0.0f;
    #pragma unroll
    for (int w = 0; w < WARPS; w++) total += warp_sums[w];

    // log(p/total) = __logf(p) - __logf(total); MUFU-based, continuous (no cliff risk)
    const float lt = __logf(total);
    if (tid < NCLS/4) {
        float4 o;
        o.x = __logf(v.x) - lt;
        o.y = __logf(v.y) - lt;
        o.z = __logf(v.z) - lt;
        o.w = __logf(v.w) - lt;
        reinterpret_cast<float4*>(out + (size_t)b * NCLS)[tid] = o;
    }
}

extern "C" void kernel_launch(void* const* d_in, const int* in_sizes, int n_in,
                              void* d_out, int out_size)
{
    // Identify inputs by element count (ordering-agnostic).
    const float* features   = nullptr;
    const float* centres    = nullptr;
    const int*   neighbours = nullptr;
    const void*  c100[2]    = {nullptr, nullptr};
    int n100 = 0;

    for (int i = 0; i < n_in; i++) {
        switch (in_sizes[i]) {
            case N_CENTRES_ELEMS: centres    = (const float*)d_in[i]; break;
            case N_FEAT_ELEMS:    features   = (const float*)d_in[i]; break;
            case N_NBR_ELEMS:     neighbours = (const int*)  d_in[i]; break;
            case N_100K:          if (n100 < 2) c100[n100++] = d_in[i]; break;
            default: break;
        }
    }

    float* out = (float*)d_out;
    gaussian_kernels_kernel<<<BATCH, THREADS>>>(features, centres,
                                                c100[0], c100[1],
                                                neighbours, out);
}

// round 10
// speedup vs baseline: 1.0412x; 1.0412x over previous
#include <cuda_runtime.h>
#include <math.h>

#define BATCH 4096
#define DIM   128
#define KNBR  200
#define NCLS  1000
#define GC    0.5f          // 1/(2*sigma^2), sigma=1
#define THREADS 128
#define WARPS   (THREADS/32)             // 4
#define GSIZE   8
#define NGROUPS (THREADS/GSIZE)          // 16 groups of 8 lanes
#define FULL_ITERS (KNBR / NGROUPS)      // 12
#define TAILG (KNBR - NGROUPS*FULL_ITERS) // 8 tail groups (groups 0..7 = warps 0..1)
#define STAGES 3

#define N_CENTRES_ELEMS 12800000
#define N_FEAT_ELEMS    524288
#define N_NBR_ELEMS     819200
#define N_100K          100000

#define FLT_MIN_NORMAL 1.17549435082228750797e-38f   // 2^-126

// Emulate aarch64 FPCR.FZ semantics: any op result that is subnormal flushes to 0.
__device__ __forceinline__ float ftz(float v) {
    return (v < FLT_MIN_NORMAL) ? 0.0f : v;   // v >= 0 in all our uses
}

// cp.async 16B, L1-bypass (.cg): GMEM -> SMEM with no register target
__device__ __forceinline__ void cp16(unsigned d, const void* s) {
    asm volatile("cp.async.cg.shared.global [%0], [%1], 16;" :: "r"(d), "l"(s) : "memory");
}
#define CP_COMMIT() asm volatile("cp.async.commit_group;" ::: "memory")
#define CP_WAIT2()  asm volatile("cp.async.wait_group 2;" ::: "memory")

__global__ __launch_bounds__(THREADS)
void gaussian_kernels_kernel(const float* __restrict__ features,
                             const float* __restrict__ centres,
                             const void*  __restrict__ cand0,   // weight OR centre_labels
                             const void*  __restrict__ cand1,   // the other one
                             const int*   __restrict__ neighbours,
                             float*       __restrict__ out)
{
    __shared__ alignas(16) float p[NCLS];                         // 4000 B
    __shared__ alignas(16) float4 tiles[STAGES][NGROUPS][DIM/4];  // 3*16*512B = 24 KB
    __shared__ float warp_sums[WARPS];

    const int b    = blockIdx.x;
    const int tid  = threadIdx.x;
    const int lane = tid & 31;
    const int grp  = tid >> 3;          // 0..15 : 8-lane group id
    const int sub  = tid & 7;           // lane within group
    const int warp = tid >> 5;

    // ---- disambiguate weight vs centre_labels by bit pattern (deterministic) ----
    const unsigned int* a0p = (const unsigned int*)cand0;
    const bool first_is_labels =
        (a0p[0] < 1000u) && (a0p[1] < 1000u) && (a0p[2] < 1000u) && (a0p[3] < 1000u);
    const float* weight        = first_is_labels ? (const float*)cand1 : (const float*)cand0;
    const int*   centre_labels = first_is_labels ? (const int*)cand0   : (const int*)cand1;

    // zero the class histogram (250 float4s over 128 threads)
    #pragma unroll
    for (int i = tid; i < NCLS/4; i += THREADS)
        ((float4*)p)[i] = make_float4(0.f, 0.f, 0.f, 0.f);

    // each lane holds 16 dims: float4s at [sub + 8*j]; group's 8 lanes = one 128B line per j
    const float4* frow = reinterpret_cast<const float4*>(features + (size_t)b * DIM);
    const float4 f0 = frow[sub + 8*0];
    const float4 f1 = frow[sub + 8*1];
    const float4 f2 = frow[sub + 8*2];
    const float4 f3 = frow[sub + 8*3];

    const int* nb = neighbours + (size_t)b * KNBR;
    const float4* cbase = reinterpret_cast<const float4*>(centres);

    // groups 0..7 (warps 0..1) run one extra iteration to cover neighbours 192..199
    const int my_iters = (grp < TAILG) ? (FULL_ITERS + 1) : FULL_ITERS;

    // ---- prolog: issue tiles for iterations 0,1,2 (one commit group each) ----
    int i_c  = nb[grp];
    int i_n1 = nb[grp + NGROUPS];
    int i_n2 = nb[grp + 2*NGROUPS];
    {
        const float4* r0 = cbase + (size_t)i_c  * (DIM/4);
        const float4* r1 = cbase + (size_t)i_n1 * (DIM/4);
        const float4* r2 = cbase + (size_t)i_n2 * (DIM/4);
        #pragma unroll
        for (int j = 0; j < 4; j++)
            cp16((unsigned)__cvta_generic_to_shared(&tiles[0][grp][sub + 8*j]), r0 + sub + 8*j);
        CP_COMMIT();
        #pragma unroll
        for (int j = 0; j < 4; j++)
            cp16((unsigned)__cvta_generic_to_shared(&tiles[1][grp][sub + 8*j]), r1 + sub + 8*j);
        CP_COMMIT();
        #pragma unroll
        for (int j = 0; j < 4; j++)
            cp16((unsigned)__cvta_generic_to_shared(&tiles[2][grp][sub + 8*j]), r2 + sub + 8*j);
        CP_COMMIT();
    }

    __syncthreads();   // guards p[] zeroing before atomics

    int stage = 0;
    for (int t = 0; t < my_iters; t++) {
        CP_WAIT2();    // tile t complete (at most 2 newer groups pending)

        // read this lane's slice of tile t from smem (conflict-free 128B rows)
        const float4 c0 = tiles[stage][grp][sub + 8*0];
        const float4 c1 = tiles[stage][grp][sub + 8*1];
        const float4 c2 = tiles[stage][grp][sub + 8*2];
        const float4 c3 = tiles[stage][grp][sub + 8*3];

        // 4 independent accumulators -> short dependency chains
        float s0 = 0.f, s1 = 0.f, s2 = 0.f, s3 = 0.f;
        float dx;
        dx = f0.x - c0.x; s0 = fmaf(dx, dx, s0);
        dx = f0.y - c0.y; s0 = fmaf(dx, dx, s0);
        dx = f0.z - c0.z; s0 = fmaf(dx, dx, s0);
        dx = f0.w - c0.w; s0 = fmaf(dx, dx, s0);
        dx = f1.x - c1.x; s1 = fmaf(dx, dx, s1);
        dx = f1.y - c1.y; s1 = fmaf(dx, dx, s1);
        dx = f1.z - c1.z; s1 = fmaf(dx, dx, s1);
        dx = f1.w - c1.w; s1 = fmaf(dx, dx, s1);
        dx = f2.x - c2.x; s2 = fmaf(dx, dx, s2);
        dx = f2.y - c2.y; s2 = fmaf(dx, dx, s2);
        dx = f2.z - c2.z; s2 = fmaf(dx, dx, s2);
        dx = f2.w - c2.w; s2 = fmaf(dx, dx, s2);
        dx = f3.x - c3.x; s3 = fmaf(dx, dx, s3);
        dx = f3.y - c3.y; s3 = fmaf(dx, dx, s3);
        dx = f3.z - c3.z; s3 = fmaf(dx, dx, s3);
        dx = f3.w - c3.w; s3 = fmaf(dx, dx, s3);
        float s = (s0 + s1) + (s2 + s3);

        // reduce within the 8-lane group
        s += __shfl_xor_sync(0xffffffffu, s, 4);
        s += __shfl_xor_sync(0xffffffffu, s, 2);
        s += __shfl_xor_sync(0xffffffffu, s, 1);

        if (sub == 0) {
            const float w   = weight[i_c];
            const int   lbl = centre_labels[i_c];
            // reference semantics (aarch64 FZ): subnormal op results flush to 0
            const float e1   = ftz(expf(-s * GC));
            const float kern = ftz(e1 * expf(w));
            if (kern != 0.0f) atomicAdd(&p[lbl], kern);
        }

        // refill the stage we just consumed with tile t+3 ((t+3)%3 == stage)
        int i_n3 = 0;
        if (t + 3 < my_iters) {
            i_n3 = nb[grp + NGROUPS * (t + 3)];
            const float4* r3 = cbase + (size_t)i_n3 * (DIM/4);
            #pragma unroll
            for (int j = 0; j < 4; j++)
                cp16((unsigned)__cvta_generic_to_shared(&tiles[stage][grp][sub + 8*j]), r3 + sub + 8*j);
        }
        CP_COMMIT();   // commit every iteration (possibly empty) -> uniform wait bookkeeping

        i_c = i_n1; i_n1 = i_n2; i_n2 = i_n3;
        stage = (stage == STAGES-1) ? 0 : stage + 1;
    }

    __syncthreads();

    // epsilon-clamp + row sum: 250 float4s over 128 threads (2 per thread, second if tid<122)
    const bool has2 = (tid + THREADS) < NCLS/4;
    float4 va = ((const float4*)p)[tid];
    float4 vb = make_float4(1e-10f, 1e-10f, 1e-10f, 1e-10f);
    va.x = (va.x == 0.0f) ? 1e-10f : va.x;
    va.y = (va.y == 0.0f) ? 1e-10f : va.y;
    va.z = (va.z == 0.0f) ? 1e-10f : va.z;
    va.w = (va.w == 0.0f) ? 1e-10f : va.w;
    float local = (va.x + va.y) + (va.z + va.w);
    if (has2) {
        vb = ((const float4*)p)[tid + THREADS];
        vb.x = (vb.x == 0.0f) ? 1e-10f : vb.x;
        vb.y = (vb.y == 0.0f) ? 1e-10f : vb.y;
        vb.z = (vb.z == 0.0f) ? 1e-10f : vb.z;
        vb.w = (vb.w == 0.0f) ? 1e-10f : vb.w;
        local += (vb.x + vb.y) + (vb.z + vb.w);
    }
    // block reduce
    local += __shfl_xor_sync(0xffffffffu, local, 16);
    local += __shfl_xor_sync(0xffffffffu, local, 8);
    local += __shfl_xor_sync(0xffffffffu, local, 4);
    local += __shfl_xor_sync(0xffffffffu, local, 2);
    local += __shfl_xor_sync(0xffffffffu, local, 1);
    if (lane == 0) warp_sums[warp] = local;
    __syncthreads();

    float total = (warp_sums[0] + warp_sums[1]) + (warp_sums[2] + warp_sums[3]);

    // log(p/total) = __logf(p) - __logf(total); MUFU-based, continuous (no cliff risk)
    const float lt = __logf(total);
    float4* orow = reinterpret_cast<float4*>(out + (size_t)b * NCLS);
    float4 oa;
    oa.x = __logf(va.x) - lt;
    oa.y = __logf(va.y) - lt;
    oa.z = __logf(va.z) - lt;
    oa.w = __logf(va.w) - lt;
    orow[tid] = oa;
    if (has2) {
        float4 ob;
        ob.x = __logf(vb.x) - lt;
        ob.y = __logf(vb.y) - lt;
        ob.z = __logf(vb.z) - lt;
        ob.w = __logf(vb.w) - lt;
        orow[tid + THREADS] = ob;
    }
}

extern "C" void kernel_launch(void* const* d_in, const int* in_sizes, int n_in,
                              void* d_out, int out_size)
{
    // Identify inputs by element count (ordering-agnostic).
    const float* features   = nullptr;
    const float* centres    = nullptr;
    const int*   neighbours = nullptr;
    const void*  c100[2]    = {nullptr, nullptr};
    int n100 = 0;

    for (int i = 0; i < n_in; i++) {
        switch (in_sizes[i]) {
            case N_CENTRES_ELEMS: centres    = (const float*)d_in[i]; break;
            case N_FEAT_ELEMS:    features   = (const float*)d_in[i]; break;
            case N_NBR_ELEMS:     neighbours = (const int*)  d_in[i]; break;
            case N_100K:          if (n100 < 2) c100[n100++] = d_in[i]; break;
            default: break;
        }
    }

    float* out = (float*)d_out;
    gaussian_kernels_kernel<<<BATCH, THREADS>>>(features, centres,
                                                c100[0], c100[1],
                                                neighbours, out);
}

// round 11
// speedup vs baseline: 1.2440x; 1.1948x over previous
#include <cuda_runtime.h>
#include <math.h>

#define BATCH 4096
#define DIM   128
#define KNBR  200
#define NCLS  1000
#define GC    0.5f          // 1/(2*sigma^2), sigma=1
#define THREADS 256
#define WARPS   (THREADS/32)
#define NGROUPS (THREADS/8)          // 32 groups of 8 lanes
#define FULL_ITERS (KNBR / NGROUPS)  // 6 full iterations; tail of 8 handled separately

#define N_CENTRES_ELEMS 12800000
#define N_FEAT_ELEMS    524288
#define N_NBR_ELEMS     819200
#define N_100K          100000

#define FLT_MIN_NORMAL 1.17549435082228750797e-38f   // 2^-126

// Emulate aarch64 FPCR.FZ semantics: any op result that is subnormal flushes to 0.
__device__ __forceinline__ float ftz(float v) {
    return (v < FLT_MIN_NORMAL) ? 0.0f : v;   // v >= 0 in all our uses
}

__global__ __launch_bounds__(THREADS)
void gaussian_kernels_kernel(const float* __restrict__ features,
                             const float* __restrict__ centres,
                             const void*  __restrict__ cand0,   // weight OR centre_labels
                             const void*  __restrict__ cand1,   // the other one
                             const int*   __restrict__ neighbours,
                             float*       __restrict__ out)
{
    __shared__ alignas(16) float p[NCLS];
    __shared__ float warp_sums[WARPS];

    const int b    = blockIdx.x;
    const int tid  = threadIdx.x;
    const int lane = tid & 31;
    const int grp  = tid >> 3;          // 0..31 : 8-lane group id
    const int sub  = tid & 7;           // lane within group
    const int warp = tid >> 5;

    // ---- disambiguate weight vs centre_labels by bit pattern (deterministic) ----
    const unsigned int* a0 = (const unsigned int*)cand0;
    const bool first_is_labels =
        (a0[0] < 1000u) && (a0[1] < 1000u) && (a0[2] < 1000u) && (a0[3] < 1000u);
    const float* weight        = first_is_labels ? (const float*)cand1 : (const float*)cand0;
    const int*   centre_labels = first_is_labels ? (const int*)cand0   : (const int*)cand1;

    // zero the class histogram (vectorized: 250 float4s)
    if (tid < NCLS/4) ((float4*)p)[tid] = make_float4(0.f, 0.f, 0.f, 0.f);

    // each lane holds 16 dims: float4s at [sub + 8*j]; a group's 8 lanes cover a 128B line.
    const float4* frow = reinterpret_cast<const float4*>(features + (size_t)b * DIM);
    const float4 f0 = frow[sub + 8*0];
    const float4 f1 = frow[sub + 8*1];
    const float4 f2 = frow[sub + 8*2];
    const float4 f3 = frow[sub + 8*3];

    __syncthreads();

    const int* nb = neighbours + (size_t)b * KNBR;

    // preload all main-loop neighbour indices (kills index->gather serial chain)
    int idx[FULL_ITERS];
    #pragma unroll
    for (int i = 0; i < FULL_ITERS; i++) idx[i] = nb[grp + NGROUPS * i];

    // prime the pipeline: loads for iteration 0
    const float4* crow0 = reinterpret_cast<const float4*>(centres + (size_t)idx[0] * DIM);
    float4 c0 = crow0[sub + 8*0];
    float4 c1 = crow0[sub + 8*1];
    float4 c2 = crow0[sub + 8*2];
    float4 c3 = crow0[sub + 8*3];

    #pragma unroll
    for (int i = 0; i < FULL_ITERS; i++) {
        // prefetch next iteration's centre row while computing this one
        float4 n0, n1, n2, n3;
        if (i + 1 < FULL_ITERS) {
            const float4* nrow = reinterpret_cast<const float4*>(centres + (size_t)idx[i+1] * DIM);
            n0 = nrow[sub + 8*0];
            n1 = nrow[sub + 8*1];
            n2 = nrow[sub + 8*2];
            n3 = nrow[sub + 8*3];
        }

        // 4 independent accumulators -> short dependency chains
        float s0 = 0.f, s1 = 0.f, s2 = 0.f, s3 = 0.f;
        float dx;
        dx = f0.x - c0.x; s0 = fmaf(dx, dx, s0);
        dx = f0.y - c0.y; s0 = fmaf(dx, dx, s0);
        dx = f0.z - c0.z; s0 = fmaf(dx, dx, s0);
        dx = f0.w - c0.w; s0 = fmaf(dx, dx, s0);
        dx = f1.x - c1.x; s1 = fmaf(dx, dx, s1);
        dx = f1.y - c1.y; s1 = fmaf(dx, dx, s1);
        dx = f1.z - c1.z; s1 = fmaf(dx, dx, s1);
        dx = f1.w - c1.w; s1 = fmaf(dx, dx, s1);
        dx = f2.x - c2.x; s2 = fmaf(dx, dx, s2);
        dx = f2.y - c2.y; s2 = fmaf(dx, dx, s2);
        dx = f2.z - c2.z; s2 = fmaf(dx, dx, s2);
        dx = f2.w - c2.w; s2 = fmaf(dx, dx, s2);
        dx = f3.x - c3.x; s3 = fmaf(dx, dx, s3);
        dx = f3.y - c3.y; s3 = fmaf(dx, dx, s3);
        dx = f3.z - c3.z; s3 = fmaf(dx, dx, s3);
        dx = f3.w - c3.w; s3 = fmaf(dx, dx, s3);
        float s = (s0 + s1) + (s2 + s3);

        // reduce within the 8-lane group
        s += __shfl_xor_sync(0xffffffffu, s, 4);
        s += __shfl_xor_sync(0xffffffffu, s, 2);
        s += __shfl_xor_sync(0xffffffffu, s, 1);

        if (sub == 0) {
            const int   n   = idx[i];
            const float w   = weight[n];
            const int   lbl = centre_labels[n];
            // reference semantics (aarch64 FZ): subnormal op results flush to 0
            const float e1   = ftz(expf(-s * GC));
            const float kern = ftz(e1 * expf(w));
            if (kern != 0.0f) atomicAdd(&p[lbl], kern);
        }

        if (i + 1 < FULL_ITERS) { c0 = n0; c1 = n1; c2 = n2; c3 = n3; }
    }

    // tail: neighbours 192..199, live only for groups 0..7 (warps 0..1, uniform branch)
    if (grp < KNBR - NGROUPS * FULL_ITERS) {
        const int n = nb[grp + NGROUPS * FULL_ITERS];
        const float4* crow = reinterpret_cast<const float4*>(centres + (size_t)n * DIM);
        const float4 t0 = crow[sub + 8*0];
        const float4 t1 = crow[sub + 8*1];
        const float4 t2 = crow[sub + 8*2];
        const float4 t3 = crow[sub + 8*3];
        float s0 = 0.f, s1 = 0.f, s2 = 0.f, s3 = 0.f;
        float dx;
        dx = f0.x - t0.x; s0 = fmaf(dx, dx, s0);
        dx = f0.y - t0.y; s0 = fmaf(dx, dx, s0);
        dx = f0.z - t0.z; s0 = fmaf(dx, dx, s0);
        dx = f0.w - t0.w; s0 = fmaf(dx, dx, s0);
        dx = f1.x - t1.x; s1 = fmaf(dx, dx, s1);
        dx = f1.y - t1.y; s1 = fmaf(dx, dx, s1);
        dx = f1.z - t1.z; s1 = fmaf(dx, dx, s1);
        dx = f1.w - t1.w; s1 = fmaf(dx, dx, s1);
        dx = f2.x - t2.x; s2 = fmaf(dx, dx, s2);
        dx = f2.y - t2.y; s2 = fmaf(dx, dx, s2);
        dx = f2.z - t2.z; s2 = fmaf(dx, dx, s2);
        dx = f2.w - t2.w; s2 = fmaf(dx, dx, s2);
        dx = f3.x - t3.x; s3 = fmaf(dx, dx, s3);
        dx = f3.y - t3.y; s3 = fmaf(dx, dx, s3);
        dx = f3.z - t3.z; s3 = fmaf(dx, dx, s3);
        dx = f3.w - t3.w; s3 = fmaf(dx, dx, s3);
        float s = (s0 + s1) + (s2 + s3);
        s += __shfl_xor_sync(0xffffffffu, s, 4);
        s += __shfl_xor_sync(0xffffffffu, s, 2);
        s += __shfl_xor_sync(0xffffffffu, s, 1);
        if (sub == 0) {
            const float w   = weight[n];
            const int   lbl = centre_labels[n];
            const float e1   = ftz(expf(-s * GC));
            const float kern = ftz(e1 * expf(w));
            if (kern != 0.0f) atomicAdd(&p[lbl], kern);
        }
    }

    __syncthreads();

    // epsilon-clamp empty bins + row sum, vectorized over 250 float4s
    float local = 0.0f;
    float4 v = make_float4(0.f, 0.f, 0.f, 0.f);
    if (tid < NCLS/4) {
        v = ((const float4*)p)[tid];
        v.x = (v.x == 0.0f) ? 1e-10f : v.x;
        v.y = (v.y == 0.0f) ? 1e-10f : v.y;
        v.z = (v.z == 0.0f) ? 1e-10f : v.z;
        v.w = (v.w == 0.0f) ? 1e-10f : v.w;
        local = (v.x + v.y) + (v.z + v.w);
    }
    // block reduce
    local += __shfl_xor_sync(0xffffffffu, local, 16);
    local += __shfl_xor_sync(0xffffffffu, local, 8);
    local += __shfl_xor_sync(0xffffffffu, local, 4);
    local += __shfl_xor_sync(0xffffffffu, local, 2);
    local += __shfl_xor_sync(0xffffffffu, local, 1);
    if (lane == 0) warp_sums[warp] = local;
    __syncthreads();

    float total = 0.0f;
    #pragma unroll
    for (int w = 0; w < WARPS; w++) total += warp_sums[w];

    // log(p/total) = __logf(p) - __logf(total). ~820 of 1000 bins are the epsilon
    // constant -> their log is one value per row. Select is bit-identical to
    // computing __logf(1e-10f) - lt per bin (even a real bin equal to 1e-10f
    // would produce the same bits), but cuts MUFU.LG2 ops per block ~5x.
    const float lt      = __logf(total);
    const float eps_log = __logf(1e-10f) - lt;
    if (tid < NCLS/4) {
        float4 o;
        o.x = (v.x == 1e-10f) ? eps_log : (__logf(v.x) - lt);
        o.y = (v.y == 1e-10f) ? eps_log : (__logf(v.y) - lt);
        o.z = (v.z == 1e-10f) ? eps_log : (__logf(v.z) - lt);
        o.w = (v.w == 1e-10f) ? eps_log : (__logf(v.w) - lt);
        reinterpret_cast<float4*>(out + (size_t)b * NCLS)[tid] = o;
    }
}

extern "C" void kernel_launch(void* const* d_in, const int* in_sizes, int n_in,
                              void* d_out, int out_size)
{
    // Identify inputs by element count (ordering-agnostic).
    const float* features   = nullptr;
    const float* centres    = nullptr;
    const int*   neighbours = nullptr;
    const void*  c100[2]    = {nullptr, nullptr};
    int n100 = 0;

    for (int i = 0; i < n_in; i++) {
        switch (in_sizes[i]) {
            case N_CENTRES_ELEMS: centres    = (const float*)d_in[i]; break;
            case N_FEAT_ELEMS:    features   = (const float*)d_in[i]; break;
            case N_NBR_ELEMS:     neighbours = (const int*)  d_in[i]; break;
            case N_100K:          if (n100 < 2) c100[n100++] = d_in[i]; break;
            default: break;
        }
    }

    float* out = (float*)d_out;
    gaussian_kernels_kernel<<<BATCH, THREADS>>>(features, centres,
                                                c100[0], c100[1],
                                                neighbours, out);
}